// round 14
// baseline (speedup 1.0000x reference)
#include <cuda_runtime.h>
#include <cuda_fp16.h>
#include <cfloat>
#include <cstdint>

#define NN 8192
#define DD 128
#define CC 64
#define FMARGIN 0.5f
#define NB 64
#define NCTAS 288          // sum over bi of ceil((64-bi)/8)
#define NTHREADS 512

typedef unsigned long long u64;

// smem byte offsets
#define S_AHI 0            // 128 x 256B swizzled
#define S_ALO 32768
#define S_BHI 65536        // + buf*32768 (2 bufs)
#define S_BLO 131072       // + buf*32768 (2 bufs)
#define S_XNA 196608       // 128 f32
#define S_TGA 197120       // 128 i32
#define S_XNB 197632       // + buf*512
#define S_TGB 198656       // + buf*512
#define S_TOT 199680

// ---------------- device scratch ----------------
__device__ __half g_h16[NN * DD];
__device__ __half g_l16[NN * DD];
__device__ float g_xn[NN];
__device__ int   g_ps[CC * NN];
__device__ int   g_hist[CC];
__device__ u64   g_pkey[NN];
__device__ u64   g_nkey[NN];
__device__ float g_part[256 * 9];

// ---------------- PTX helpers ----------------
__device__ __forceinline__ uint32_t smem_u32(const void* p) {
    uint32_t a;
    asm("{ .reg .u64 t; cvta.to.shared.u64 t, %1; cvt.u32.u64 %0, t; }" : "=r"(a) : "l"(p));
    return a;
}
__device__ __forceinline__ uint64_t gbl_u64(const void* p) {
    uint64_t a;
    asm("cvta.to.global.u64 %0, %1;" : "=l"(a) : "l"(p));
    return a;
}
__device__ __forceinline__ void cpa16(uint32_t dst, uint64_t src) {
    asm volatile("cp.async.cg.shared.global [%0], [%1], 16;" :: "r"(dst), "l"(src));
}
__device__ __forceinline__ void cpa4(uint32_t dst, uint64_t src) {
    asm volatile("cp.async.ca.shared.global [%0], [%1], 4;" :: "r"(dst), "l"(src));
}
#define CPA_COMMIT() asm volatile("cp.async.commit_group;" ::: "memory")
#define CPA_WAIT0()  asm volatile("cp.async.wait_group 0;" ::: "memory")

__device__ __forceinline__ void ldsm4(uint32_t* r, uint32_t addr) {
    asm volatile("ldmatrix.sync.aligned.m8n8.x4.shared.b16 {%0,%1,%2,%3}, [%4];"
                 : "=r"(r[0]), "=r"(r[1]), "=r"(r[2]), "=r"(r[3]) : "r"(addr));
}
__device__ __forceinline__ void mma_f16(float* d, const uint32_t* a, uint32_t b0, uint32_t b1) {
    asm volatile(
        "mma.sync.aligned.m16n8k16.row.col.f32.f16.f16.f32 "
        "{%0,%1,%2,%3}, {%4,%5,%6,%7}, {%8,%9}, {%0,%1,%2,%3};"
        : "+f"(d[0]), "+f"(d[1]), "+f"(d[2]), "+f"(d[3])
        : "r"(a[0]), "r"(a[1]), "r"(a[2]), "r"(a[3]), "r"(b0), "r"(b1));
}
// order-preserving float->u32 encoding (monotone, no NaNs in data)
__device__ __forceinline__ uint32_t encf(float f) {
    uint32_t u = __float_as_uint(f);
    return (u & 0x80000000u) ? ~u : (u | 0x80000000u);
}
// fire-and-forget global reductions (return value unused -> RED)
__device__ __forceinline__ void red_max(u64* p, u64 k) { atomicMax(p, k); }
__device__ __forceinline__ void red_min(u64* p, u64 k) { atomicMin(p, k); }

// ---------------- K0: fp16 split + norms + key init (fused) ----------------
__global__ void prep_kernel(const float* __restrict__ x) {
    int row = blockIdx.x * blockDim.x + threadIdx.x;
    g_pkey[row] = 0ull;                 // reset per graph replay
    g_nkey[row] = ~0ull;
    const float4* xr = reinterpret_cast<const float4*>(x) + (size_t)row * 32;
    __half2* hr = reinterpret_cast<__half2*>(g_h16) + (size_t)row * 64;
    __half2* lr = reinterpret_cast<__half2*>(g_l16) + (size_t)row * 64;
    float s = 0.0f;
    #pragma unroll
    for (int q = 0; q < 32; q++) {
        float4 v = xr[q];
        __half hx = __float2half_rn(v.x), hy = __float2half_rn(v.y);
        __half hz = __float2half_rn(v.z), hw = __float2half_rn(v.w);
        float lx = v.x - __half2float(hx), ly = v.y - __half2float(hy);
        float lz = v.z - __half2float(hz), lw = v.w - __half2float(hw);
        hr[2 * q + 0] = __halves2half2(hx, hy);
        hr[2 * q + 1] = __halves2half2(hz, hw);
        lr[2 * q + 0] = __halves2half2(__float2half_rn(lx), __float2half_rn(ly));
        lr[2 * q + 1] = __halves2half2(__float2half_rn(lz), __float2half_rn(lw));
        s = fmaf(v.x, v.x, s); s = fmaf(v.y, v.y, s);
        s = fmaf(v.z, v.z, s); s = fmaf(v.w, v.w, s);
    }
    g_xn[row] = s;
}

// ---------------- K1: per-class inclusive prefix counts (1024 thr) ----------------
__global__ void prefix_kernel(const int* __restrict__ tg) {
    int c = blockIdx.x;
    __shared__ int wsum[32];
    __shared__ int wpre[32];
    __shared__ int stot;
    int tid = threadIdx.x;
    int lane = tid & 31, wid = tid >> 5;
    int run = 0;
    for (int base = 0; base < NN; base += 1024) {
        int f = (tg[base + tid] == c) ? 1 : 0;
        int s = f;
        #pragma unroll
        for (int o = 1; o < 32; o <<= 1) {
            int v = __shfl_up_sync(0xffffffffu, s, o);
            if (lane >= o) s += v;
        }
        if (lane == 31) wsum[wid] = s;
        __syncthreads();
        if (wid == 0) {
            int v = wsum[lane];
            int inc = v;
            #pragma unroll
            for (int o = 1; o < 32; o <<= 1) {
                int w = __shfl_up_sync(0xffffffffu, inc, o);
                if (lane >= o) inc += w;
            }
            wpre[lane] = inc - v;       // exclusive prefix of warp sums
            if (lane == 31) stot = inc;
        }
        __syncthreads();
        g_ps[c * NN + base + tid] = run + wpre[wid] + s;
        run += stot;
        __syncthreads();
    }
    if (tid == 0) g_hist[c] = run;
}

// load a 128-row fp16 block (hi+lo) into swizzled smem via cp.async (512 thr)
__device__ __forceinline__ void load_blk(uint64_t GH, uint64_t GL,
                                         uint32_t dhi, uint32_t dlo,
                                         int rowbase, int tid) {
    #pragma unroll
    for (int u = 0; u < 4; u++) {
        int idx = tid + u * NTHREADS;              // 0..2047
        int r = idx >> 4, kc = idx & 15;
        uint64_t off = (((size_t)(rowbase + r) * DD + kc * 8) << 1);
        uint32_t so = r * 256 + (((uint32_t)kc ^ (r & 7)) << 4);
        cpa16(dhi + so, GH + off);
        cpa16(dlo + so, GL + off);
    }
}

// ---------------- K2: triangular streamed fp16-split mma, 16 warps ----------------
__global__ void __launch_bounds__(NTHREADS, 1)
dist_mma_kernel(const int* __restrict__ tg) {
    extern __shared__ char sm[];
    const uint32_t sb = smem_u32(sm);
    const uint64_t GH = gbl_u64(g_h16);
    const uint64_t GL = gbl_u64(g_l16);
    const uint64_t GX = gbl_u64(g_xn);
    const uint64_t GT = gbl_u64(tg);

    // decode blockIdx.x -> (bi, chunk)
    int bi = 0, rem = blockIdx.x, ch;
    while (rem >= (ch = ((NB - bi + 7) >> 3))) { rem -= ch; bi++; }
    const int jblk0 = bi + rem * 8;
    const int jc = min(8, NB - jblk0);
    const int ib = bi * 128;

    const int tid = threadIdx.x;
    const int lane = tid & 31;
    const int wid = tid >> 5;            // 0..15
    const int wm = wid >> 2;             // 0..3 row group (32 rows)
    const int wn = wid & 3;              // 0..3 col group (32 cols)
    const int tq = lane & 3;
    const int rg = lane >> 2;
    const uint32_t x7 = lane & 7;
    const uint32_t ahit = lane >> 4;              // row-half select for ldmatrix
    const uint32_t bhit = (lane >> 3) & 1;        // k-chunk select for B ldmatrix
    const uint32_t arow0 = wm * 32 + (lane & 15);
    const uint32_t arow1 = arow0 + 16;

    // initial loads: A(hi+lo) + metaA + B(tile0) + metaB0
    load_blk(GH, GL, sb + S_AHI, sb + S_ALO, ib, tid);
    if (tid < 128)      cpa4(sb + S_XNA + tid * 4, GX + ((size_t)(ib + tid) << 2));
    else if (tid < 256) cpa4(sb + S_TGA + (tid - 128) * 4, GT + ((size_t)(ib + tid - 128) << 2));
    load_blk(GH, GL, sb + S_BHI, sb + S_BLO, jblk0 * 128, tid);
    if (tid < 128)      cpa4(sb + S_XNB + tid * 4, GX + ((size_t)(jblk0 * 128 + tid) << 2));
    else if (tid < 256) cpa4(sb + S_TGB + (tid - 128) * 4, GT + ((size_t)(jblk0 * 128 + tid - 128) << 2));
    CPA_COMMIT();
    CPA_WAIT0();
    __syncthreads();

    float xna[4]; int tga[4];
    #pragma unroll
    for (int r = 0; r < 4; r++) {
        int row = wm * 32 + (r >> 1) * 16 + (r & 1) * 8 + rg;
        xna[r] = *reinterpret_cast<const float*>(sm + S_XNA + row * 4);
        tga[r] = *reinterpret_cast<const int*>(sm + S_TGA + row * 4);
    }
    float rpv[4], rnv[4]; int rpi[4], rni[4];
    #pragma unroll
    for (int r = 0; r < 4; r++) { rpv[r] = -FLT_MAX; rnv[r] = FLT_MAX; rpi[r] = NN; rni[r] = NN; }

    for (int t = 0; t < jc; t++) {
        const int buf = t & 1;
        const int bj = jblk0 + t;
        const int jb = bj * 128;

        // prefetch next B tile + meta into the other buffer
        if (t + 1 < jc) {
            const int nb2 = (t + 1) & 1;
            load_blk(GH, GL, sb + S_BHI + nb2 * 32768, sb + S_BLO + nb2 * 32768,
                     (bj + 1) * 128, tid);
            if (tid < 128)      cpa4(sb + S_XNB + nb2 * 512 + tid * 4,
                                     GX + ((size_t)((bj + 1) * 128 + tid) << 2));
            else if (tid < 256) cpa4(sb + S_TGB + nb2 * 512 + (tid - 128) * 4,
                                     GT + ((size_t)((bj + 1) * 128 + tid - 128) << 2));
            CPA_COMMIT();
        }

        // ---- compute 128x128 tile: warp tile 32x32, 3 pass-separated loops ----
        float acc[2][4][4];
        #pragma unroll
        for (int mi = 0; mi < 2; mi++)
            #pragma unroll
            for (int ni = 0; ni < 4; ni++)
                #pragma unroll
                for (int c = 0; c < 4; c++) acc[mi][ni][c] = 0.0f;

        const uint32_t bhb = sb + S_BHI + buf * 32768;
        const uint32_t blb = sb + S_BLO + buf * 32768;
        #pragma unroll
        for (int ks = 0; ks < 8; ks++) {
            uint32_t ah[2][4], al[2][4], bh[2][4], bl[2][4];
            const uint32_t swzA = (((uint32_t)(2 * ks) + ahit) ^ x7) << 4;
            const uint32_t swzB = (((uint32_t)(2 * ks) + bhit) ^ x7) << 4;
            ldsm4(ah[0], sb + S_AHI + arow0 * 256 + swzA);
            ldsm4(ah[1], sb + S_AHI + arow1 * 256 + swzA);
            ldsm4(al[0], sb + S_ALO + arow0 * 256 + swzA);
            ldsm4(al[1], sb + S_ALO + arow1 * 256 + swzA);
            #pragma unroll
            for (int q = 0; q < 2; q++) {
                uint32_t brow = wn * 32 + q * 16 + x7 + (ahit << 3);
                ldsm4(bh[q], bhb + brow * 256 + swzB);
                ldsm4(bl[q], blb + brow * 256 + swzB);
            }
            // pass 1: hi*hi — 8 independent MMAs
            #pragma unroll
            for (int mi = 0; mi < 2; mi++)
                #pragma unroll
                for (int ni = 0; ni < 4; ni++) {
                    const int q = ni >> 1, p = (ni & 1) * 2;
                    mma_f16(acc[mi][ni], ah[mi], bh[q][p], bh[q][p + 1]);
                }
            // pass 2: hi*lo
            #pragma unroll
            for (int mi = 0; mi < 2; mi++)
                #pragma unroll
                for (int ni = 0; ni < 4; ni++) {
                    const int q = ni >> 1, p = (ni & 1) * 2;
                    mma_f16(acc[mi][ni], ah[mi], bl[q][p], bl[q][p + 1]);
                }
            // pass 3: lo*hi
            #pragma unroll
            for (int mi = 0; mi < 2; mi++)
                #pragma unroll
                for (int ni = 0; ni < 4; ni++) {
                    const int q = ni >> 1, p = (ni & 1) * 2;
                    mma_f16(acc[mi][ni], al[mi], bh[q][p], bh[q][p + 1]);
                }
        }

        // ---- epilogue: row side in regs; col side = in-thread fold + RED ----
        const float* sxb = reinterpret_cast<const float*>(sm + S_XNB + buf * 512);
        const int*   stb = reinterpret_cast<const int*>(sm + S_TGB + buf * 512);
        const bool offd = (bj > bi);

        #pragma unroll
        for (int ni = 0; ni < 4; ni++) {
            const int c0 = wn * 32 + ni * 8 + 2 * tq;      // local col 0..127
            const float xb0 = sxb[c0], xb1 = sxb[c0 + 1];
            const int tb0 = stb[c0], tb1 = stb[c0 + 1];
            const int j0 = jb + c0;
            // col-side per-column-stream fold state (value + source row)
            float bp0 = -FLT_MAX, bp1 = -FLT_MAX, bn0 = FLT_MAX, bn1 = FLT_MAX;
            int ip0 = 0, ip1 = 0, in0 = 0, in1 = 0;
            #pragma unroll
            for (int mi = 0; mi < 2; mi++) {
                #pragma unroll
                for (int h = 0; h < 2; h++) {
                    const int ri = mi * 2 + h;
                    const int gi = ib + wm * 32 + mi * 16 + h * 8 + rg;
                    const float d0 = acc[mi][ni][h * 2 + 0];
                    const float d1 = acc[mi][ni][h * 2 + 1];
                    const bool same0 = (tb0 == tga[ri]);
                    const bool same1 = (tb1 == tga[ri]);
                    // row side: candidate j for row i
                    float s0 = fmaf(-2.0f, d0, xb0);
                    float s1 = fmaf(-2.0f, d1, xb1);
                    if (same0) { if (s0 > rpv[ri]) { rpv[ri] = s0; rpi[ri] = j0; } }
                    else       { if (s0 < rnv[ri]) { rnv[ri] = s0; rni[ri] = j0; } }
                    if (same1) { if (s1 > rpv[ri]) { rpv[ri] = s1; rpi[ri] = j0 + 1; } }
                    else       { if (s1 < rnv[ri]) { rnv[ri] = s1; rni[ri] = j0 + 1; } }
                    // col side: candidate i for column j (ascending gi -> first-wins ties)
                    if (offd) {
                        float t0 = fmaf(-2.0f, d0, xna[ri]);
                        float t1 = fmaf(-2.0f, d1, xna[ri]);
                        if (same0) { if (t0 > bp0) { bp0 = t0; ip0 = gi; } }
                        else       { if (t0 < bn0) { bn0 = t0; in0 = gi; } }
                        if (same1) { if (t1 > bp1) { bp1 = t1; ip1 = gi; } }
                        else       { if (t1 < bn1) { bn1 = t1; in1 = gi; } }
                    }
                }
            }
            if (offd) {
                if (bp0 > -FLT_MAX)
                    red_max(&g_pkey[j0], ((u64)encf(bp0) << 32) | (uint32_t)(~(uint32_t)ip0));
                if (bn0 < FLT_MAX)
                    red_min(&g_nkey[j0], ((u64)encf(bn0) << 32) | (uint32_t)in0);
                if (bp1 > -FLT_MAX)
                    red_max(&g_pkey[j0 + 1], ((u64)encf(bp1) << 32) | (uint32_t)(~(uint32_t)ip1));
                if (bn1 < FLT_MAX)
                    red_min(&g_nkey[j0 + 1], ((u64)encf(bn1) << 32) | (uint32_t)in1);
            }
        }

        CPA_WAIT0();
        __syncthreads();
    }

    // ---- flush row-side running state ----
    #pragma unroll
    for (int r = 0; r < 4; r++) {
        float pv = rpv[r]; int pi2 = rpi[r];
        float nv = rnv[r]; int ni2 = rni[r];
        #pragma unroll
        for (int off = 1; off <= 2; off <<= 1) {
            float ov = __shfl_xor_sync(0xffffffffu, pv, off);
            int oi = __shfl_xor_sync(0xffffffffu, pi2, off);
            if (ov > pv || (ov == pv && oi < pi2)) { pv = ov; pi2 = oi; }
            ov = __shfl_xor_sync(0xffffffffu, nv, off);
            oi = __shfl_xor_sync(0xffffffffu, ni2, off);
            if (ov < nv || (ov == nv && oi < ni2)) { nv = ov; ni2 = oi; }
        }
        if (tq == 0) {
            int row = ib + wm * 32 + (r >> 1) * 16 + (r & 1) * 8 + rg;
            red_max(&g_pkey[row], ((u64)encf(pv) << 32) | (uint32_t)(~(uint32_t)pi2));
            red_min(&g_nkey[row], ((u64)encf(nv) << 32) | (uint32_t)ni2);
        }
    }
}

// ---------------- K3: decode keys, gather triplets, partial sums (256 x 32) ----------------
__global__ void terms_kernel(const float* __restrict__ x, const int* __restrict__ tg) {
    int tid = threadIdx.x;
    int row = blockIdx.x * 32 + tid;

    u64 pk = g_pkey[row], nk = g_nkey[row];
    int gp = (int)(~(uint32_t)pk);
    int gn = (int)((uint32_t)nk);

    int t = tg[row];
    int cs = g_hist[t];
    float vf = (cs > 1 && (NN - cs) >= 1) ? 1.0f : 0.0f;
    gp = min(max(gp, 0), NN - 1);
    gn = min(max(gn, 0), NN - 1);
    int ppos = g_ps[t * NN + gp] - 1;
    int pneg = gn - g_ps[t * NN + gn];
    ppos = min(max(ppos, 0), NN - 1);
    pneg = min(max(pneg, 0), NN - 1);

    const float4* A = reinterpret_cast<const float4*>(x) + (size_t)row * 32;
    const float4* P = reinterpret_cast<const float4*>(x) + (size_t)ppos * 32;
    const float4* Q = reinterpret_cast<const float4*>(x) + (size_t)pneg * 32;
    float ap = 0, an = 0, npd = 0, l1a = 0, l1p = 0, l1n = 0;
    #pragma unroll
    for (int q = 0; q < 32; q++) {
        float4 a = A[q], p = P[q], n = Q[q];
        float d;
        d = a.x - p.x; ap = fmaf(d, d, ap);
        d = a.y - p.y; ap = fmaf(d, d, ap);
        d = a.z - p.z; ap = fmaf(d, d, ap);
        d = a.w - p.w; ap = fmaf(d, d, ap);
        d = a.x - n.x; an = fmaf(d, d, an);
        d = a.y - n.y; an = fmaf(d, d, an);
        d = a.z - n.z; an = fmaf(d, d, an);
        d = a.w - n.w; an = fmaf(d, d, an);
        d = p.x - n.x; npd = fmaf(d, d, npd);
        d = p.y - n.y; npd = fmaf(d, d, npd);
        d = p.z - n.z; npd = fmaf(d, d, npd);
        d = p.w - n.w; npd = fmaf(d, d, npd);
        l1a += fabsf(a.x) + fabsf(a.y) + fabsf(a.z) + fabsf(a.w);
        l1p += fabsf(p.x) + fabsf(p.y) + fabsf(p.z) + fabsf(p.w);
        l1n += fabsf(n.x) + fabsf(n.y) + fabsf(n.z) + fabsf(n.w);
    }
    float tl = fmaxf(ap - an + FMARGIN, 0.0f) * vf;

    float vals[9];
    vals[0] = tl;
    vals[1] = (tl > 0.0f) ? 1.0f : 0.0f;
    vals[2] = l1a * vf;
    vals[3] = l1p * vf;
    vals[4] = l1n * vf;
    vals[5] = ap * vf;
    vals[6] = an * vf;
    vals[7] = (ap - an - npd) * vf;
    vals[8] = vf;

    #pragma unroll
    for (int k = 0; k < 9; k++) {
        float v = vals[k];
        #pragma unroll
        for (int o = 16; o > 0; o >>= 1) v += __shfl_down_sync(0xffffffffu, v, o);
        if (tid == 0) g_part[blockIdx.x * 9 + k] = v;
    }
}

// ---------------- K4: finalize (parallel staging, ascending-block order) ----------------
__global__ void final_kernel(float* __restrict__ out, int out_size) {
    __shared__ float sp[256 * 9];
    __shared__ float s9[9];
    __shared__ float r[6];
    int tid = threadIdx.x;
    for (int i = tid; i < 256 * 9; i += blockDim.x) sp[i] = g_part[i];
    __syncthreads();
    if (tid < 9) {
        float s = 0.0f;
        for (int b = 0; b < 256; b++) s += sp[b * 9 + tid];
        s9[tid] = s;
    }
    __syncthreads();
    if (tid == 0) {
        float vcount = s9[8];
        float inv = (vcount > 0.0f) ? (1.0f / vcount) : 0.0f;
        float trip = (s9[1] > 0.0f) ? (s9[0] / s9[1]) : (s9[0] * inv);
        float sparse = (s9[2] + s9[3] + s9[4]) * inv * (1.0f / 3.0f);
        float pw = s9[7] * inv;
        if (pw < 0.0f) pw = 0.0f;
        r[0] = trip; r[1] = sparse; r[2] = pw;
        r[3] = vcount; r[4] = s9[5] * inv; r[5] = s9[6] * inv;
    }
    __syncthreads();
    for (int i = tid; i < out_size; i += blockDim.x)
        out[i] = (i < 6) ? r[i] : 0.0f;
}

// ---------------- launch ----------------
extern "C" void kernel_launch(void* const* d_in, const int* in_sizes, int n_in,
                              void* d_out, int out_size) {
    const float* x = (const float*)d_in[0];
    const int* tg = (const int*)d_in[1];

    cudaFuncSetAttribute(dist_mma_kernel, cudaFuncAttributeMaxDynamicSharedMemorySize,
                         S_TOT);

    prep_kernel<<<64, 128>>>(x);
    prefix_kernel<<<CC, 1024>>>(tg);
    dist_mma_kernel<<<NCTAS, NTHREADS, S_TOT>>>(tg);
    terms_kernel<<<256, 32>>>(x, tg);
    final_kernel<<<1, 1024>>>((float*)d_out, out_size);
}

// round 15
// speedup vs baseline: 1.0305x; 1.0305x over previous
#include <cuda_runtime.h>
#include <cuda_fp16.h>
#include <cfloat>
#include <cstdint>

#define NN 8192
#define DD 128
#define CC 64
#define FMARGIN 0.5f
#define NB 64
#define NCTAS 288          // sum over bi of ceil((64-bi)/8)
#define NTHREADS 512

typedef unsigned long long u64;

// smem byte offsets
#define S_AHI 0            // 128 x 256B swizzled
#define S_ALO 32768
#define S_BHI 65536        // + buf*32768 (2 bufs)
#define S_BLO 131072       // + buf*32768 (2 bufs)
#define S_XNA 196608       // 128 f32
#define S_TGA 197120       // 128 i32
#define S_XNB 197632       // + buf*512
#define S_TGB 198656       // + buf*512
#define S_TOT 199680

// ---------------- device scratch ----------------
__device__ __half g_h16[NN * DD];
__device__ __half g_l16[NN * DD];
__device__ float g_xn[NN];
__device__ int   g_ps[CC * NN];
__device__ int   g_hist[CC];
__device__ u64   g_pkey[NN];
__device__ u64   g_nkey[NN];
__device__ float g_part[256 * 9];

// ---------------- PTX helpers ----------------
__device__ __forceinline__ uint32_t smem_u32(const void* p) {
    uint32_t a;
    asm("{ .reg .u64 t; cvta.to.shared.u64 t, %1; cvt.u32.u64 %0, t; }" : "=r"(a) : "l"(p));
    return a;
}
__device__ __forceinline__ uint64_t gbl_u64(const void* p) {
    uint64_t a;
    asm("cvta.to.global.u64 %0, %1;" : "=l"(a) : "l"(p));
    return a;
}
__device__ __forceinline__ void cpa16(uint32_t dst, uint64_t src) {
    asm volatile("cp.async.cg.shared.global [%0], [%1], 16;" :: "r"(dst), "l"(src));
}
__device__ __forceinline__ void cpa4(uint32_t dst, uint64_t src) {
    asm volatile("cp.async.ca.shared.global [%0], [%1], 4;" :: "r"(dst), "l"(src));
}
#define CPA_COMMIT() asm volatile("cp.async.commit_group;" ::: "memory")
#define CPA_WAIT0()  asm volatile("cp.async.wait_group 0;" ::: "memory")

__device__ __forceinline__ void ldsm4(uint32_t* r, uint32_t addr) {
    asm volatile("ldmatrix.sync.aligned.m8n8.x4.shared.b16 {%0,%1,%2,%3}, [%4];"
                 : "=r"(r[0]), "=r"(r[1]), "=r"(r[2]), "=r"(r[3]) : "r"(addr));
}
__device__ __forceinline__ void mma_f16(float* d, const uint32_t* a, uint32_t b0, uint32_t b1) {
    asm volatile(
        "mma.sync.aligned.m16n8k16.row.col.f32.f16.f16.f32 "
        "{%0,%1,%2,%3}, {%4,%5,%6,%7}, {%8,%9}, {%0,%1,%2,%3};"
        : "+f"(d[0]), "+f"(d[1]), "+f"(d[2]), "+f"(d[3])
        : "r"(a[0]), "r"(a[1]), "r"(a[2]), "r"(a[3]), "r"(b0), "r"(b1));
}
// order-preserving float->u32 encoding (monotone, no NaNs in data)
__device__ __forceinline__ uint32_t encf(float f) {
    uint32_t u = __float_as_uint(f);
    return (u & 0x80000000u) ? ~u : (u | 0x80000000u);
}
// fire-and-forget global reductions (return value unused -> RED)
__device__ __forceinline__ void red_max(u64* p, u64 k) { atomicMax(p, k); }
__device__ __forceinline__ void red_min(u64* p, u64 k) { atomicMin(p, k); }

// ---------------- K0: fp16 split + norms + key init (2 lanes per row) ----------------
__global__ void prep_kernel(const float* __restrict__ x) {
    int tid = threadIdx.x;                       // 0..255
    int row = blockIdx.x * 128 + (tid >> 1);
    int half = tid & 1;
    if (half == 0) { g_pkey[row] = 0ull; g_nkey[row] = ~0ull; }
    const float4* xr = reinterpret_cast<const float4*>(x) + (size_t)row * 32 + half * 16;
    __half2* hr = reinterpret_cast<__half2*>(g_h16) + (size_t)row * 64 + half * 32;
    __half2* lr = reinterpret_cast<__half2*>(g_l16) + (size_t)row * 64 + half * 32;
    float s = 0.0f;
    #pragma unroll
    for (int q = 0; q < 16; q++) {
        float4 v = xr[q];
        __half hx = __float2half_rn(v.x), hy = __float2half_rn(v.y);
        __half hz = __float2half_rn(v.z), hw = __float2half_rn(v.w);
        float lx = v.x - __half2float(hx), ly = v.y - __half2float(hy);
        float lz = v.z - __half2float(hz), lw = v.w - __half2float(hw);
        hr[2 * q + 0] = __halves2half2(hx, hy);
        hr[2 * q + 1] = __halves2half2(hz, hw);
        lr[2 * q + 0] = __halves2half2(__float2half_rn(lx), __float2half_rn(ly));
        lr[2 * q + 1] = __halves2half2(__float2half_rn(lz), __float2half_rn(lw));
        s = fmaf(v.x, v.x, s); s = fmaf(v.y, v.y, s);
        s = fmaf(v.z, v.z, s); s = fmaf(v.w, v.w, s);
    }
    s += __shfl_xor_sync(0xffffffffu, s, 1);
    if (half == 0) g_xn[row] = s;
}

// ---------------- K1: per-class inclusive prefix counts (1024 thr) ----------------
__global__ void prefix_kernel(const int* __restrict__ tg) {
    int c = blockIdx.x;
    __shared__ int wsum[32];
    __shared__ int wpre[32];
    __shared__ int stot;
    int tid = threadIdx.x;
    int lane = tid & 31, wid = tid >> 5;
    int run = 0;
    for (int base = 0; base < NN; base += 1024) {
        int f = (tg[base + tid] == c) ? 1 : 0;
        int s = f;
        #pragma unroll
        for (int o = 1; o < 32; o <<= 1) {
            int v = __shfl_up_sync(0xffffffffu, s, o);
            if (lane >= o) s += v;
        }
        if (lane == 31) wsum[wid] = s;
        __syncthreads();
        if (wid == 0) {
            int v = wsum[lane];
            int inc = v;
            #pragma unroll
            for (int o = 1; o < 32; o <<= 1) {
                int w = __shfl_up_sync(0xffffffffu, inc, o);
                if (lane >= o) inc += w;
            }
            wpre[lane] = inc - v;       // exclusive prefix of warp sums
            if (lane == 31) stot = inc;
        }
        __syncthreads();
        g_ps[c * NN + base + tid] = run + wpre[wid] + s;
        run += stot;
        __syncthreads();
    }
    if (tid == 0) g_hist[c] = run;
}

// load a 128-row fp16 block (hi+lo) into swizzled smem via cp.async (512 thr)
__device__ __forceinline__ void load_blk(uint64_t GH, uint64_t GL,
                                         uint32_t dhi, uint32_t dlo,
                                         int rowbase, int tid) {
    #pragma unroll
    for (int u = 0; u < 4; u++) {
        int idx = tid + u * NTHREADS;              // 0..2047
        int r = idx >> 4, kc = idx & 15;
        uint64_t off = (((size_t)(rowbase + r) * DD + kc * 8) << 1);
        uint32_t so = r * 256 + (((uint32_t)kc ^ (r & 7)) << 4);
        cpa16(dhi + so, GH + off);
        cpa16(dlo + so, GL + off);
    }
}

// ---------------- K2: triangular streamed fp16-split mma, 16 warps ----------------
__global__ void __launch_bounds__(NTHREADS, 1)
dist_mma_kernel(const int* __restrict__ tg) {
    extern __shared__ char sm[];
    const uint32_t sb = smem_u32(sm);
    const uint64_t GH = gbl_u64(g_h16);
    const uint64_t GL = gbl_u64(g_l16);
    const uint64_t GX = gbl_u64(g_xn);
    const uint64_t GT = gbl_u64(tg);

    // decode blockIdx.x -> (bi, chunk)
    int bi = 0, rem = blockIdx.x, ch;
    while (rem >= (ch = ((NB - bi + 7) >> 3))) { rem -= ch; bi++; }
    const int jblk0 = bi + rem * 8;
    const int jc = min(8, NB - jblk0);
    const int ib = bi * 128;

    const int tid = threadIdx.x;
    const int lane = tid & 31;
    const int wid = tid >> 5;            // 0..15
    const int wm = wid >> 2;             // 0..3 row group (32 rows)
    const int wn = wid & 3;              // 0..3 col group (32 cols)
    const int tq = lane & 3;
    const int rg = lane >> 2;
    const uint32_t x7 = lane & 7;
    const uint32_t ahit = lane >> 4;              // row-half select for ldmatrix
    const uint32_t bhit = (lane >> 3) & 1;        // k-chunk select for B ldmatrix
    const uint32_t arow0 = wm * 32 + (lane & 15);
    const uint32_t arow1 = arow0 + 16;

    // initial loads: A(hi+lo) + metaA + B(tile0) + metaB0
    load_blk(GH, GL, sb + S_AHI, sb + S_ALO, ib, tid);
    if (tid < 128)      cpa4(sb + S_XNA + tid * 4, GX + ((size_t)(ib + tid) << 2));
    else if (tid < 256) cpa4(sb + S_TGA + (tid - 128) * 4, GT + ((size_t)(ib + tid - 128) << 2));
    load_blk(GH, GL, sb + S_BHI, sb + S_BLO, jblk0 * 128, tid);
    if (tid < 128)      cpa4(sb + S_XNB + tid * 4, GX + ((size_t)(jblk0 * 128 + tid) << 2));
    else if (tid < 256) cpa4(sb + S_TGB + (tid - 128) * 4, GT + ((size_t)(jblk0 * 128 + tid - 128) << 2));
    CPA_COMMIT();
    CPA_WAIT0();
    __syncthreads();

    float xna[4]; int tga[4];
    #pragma unroll
    for (int r = 0; r < 4; r++) {
        int row = wm * 32 + (r >> 1) * 16 + (r & 1) * 8 + rg;
        xna[r] = *reinterpret_cast<const float*>(sm + S_XNA + row * 4);
        tga[r] = *reinterpret_cast<const int*>(sm + S_TGA + row * 4);
    }
    float rpv[4], rnv[4]; int rpi[4], rni[4];
    #pragma unroll
    for (int r = 0; r < 4; r++) { rpv[r] = -FLT_MAX; rnv[r] = FLT_MAX; rpi[r] = NN; rni[r] = NN; }

    for (int t = 0; t < jc; t++) {
        const int buf = t & 1;
        const int bj = jblk0 + t;
        const int jb = bj * 128;

        // prefetch next B tile + meta into the other buffer
        if (t + 1 < jc) {
            const int nb2 = (t + 1) & 1;
            load_blk(GH, GL, sb + S_BHI + nb2 * 32768, sb + S_BLO + nb2 * 32768,
                     (bj + 1) * 128, tid);
            if (tid < 128)      cpa4(sb + S_XNB + nb2 * 512 + tid * 4,
                                     GX + ((size_t)((bj + 1) * 128 + tid) << 2));
            else if (tid < 256) cpa4(sb + S_TGB + nb2 * 512 + (tid - 128) * 4,
                                     GT + ((size_t)((bj + 1) * 128 + tid - 128) << 2));
            CPA_COMMIT();
        }

        // ---- compute 128x128 tile: warp tile 32x32, 3 pass-separated loops ----
        float acc[2][4][4];
        #pragma unroll
        for (int mi = 0; mi < 2; mi++)
            #pragma unroll
            for (int ni = 0; ni < 4; ni++)
                #pragma unroll
                for (int c = 0; c < 4; c++) acc[mi][ni][c] = 0.0f;

        const uint32_t bhb = sb + S_BHI + buf * 32768;
        const uint32_t blb = sb + S_BLO + buf * 32768;
        #pragma unroll
        for (int ks = 0; ks < 8; ks++) {
            uint32_t ah[2][4], al[2][4], bh[2][4], bl[2][4];
            const uint32_t swzA = (((uint32_t)(2 * ks) + ahit) ^ x7) << 4;
            const uint32_t swzB = (((uint32_t)(2 * ks) + bhit) ^ x7) << 4;
            ldsm4(ah[0], sb + S_AHI + arow0 * 256 + swzA);
            ldsm4(ah[1], sb + S_AHI + arow1 * 256 + swzA);
            ldsm4(al[0], sb + S_ALO + arow0 * 256 + swzA);
            ldsm4(al[1], sb + S_ALO + arow1 * 256 + swzA);
            #pragma unroll
            for (int q = 0; q < 2; q++) {
                uint32_t brow = wn * 32 + q * 16 + x7 + (ahit << 3);
                ldsm4(bh[q], bhb + brow * 256 + swzB);
                ldsm4(bl[q], blb + brow * 256 + swzB);
            }
            // pass 1: hi*hi — 8 independent MMAs
            #pragma unroll
            for (int mi = 0; mi < 2; mi++)
                #pragma unroll
                for (int ni = 0; ni < 4; ni++) {
                    const int q = ni >> 1, p = (ni & 1) * 2;
                    mma_f16(acc[mi][ni], ah[mi], bh[q][p], bh[q][p + 1]);
                }
            // pass 2: hi*lo
            #pragma unroll
            for (int mi = 0; mi < 2; mi++)
                #pragma unroll
                for (int ni = 0; ni < 4; ni++) {
                    const int q = ni >> 1, p = (ni & 1) * 2;
                    mma_f16(acc[mi][ni], ah[mi], bl[q][p], bl[q][p + 1]);
                }
            // pass 3: lo*hi
            #pragma unroll
            for (int mi = 0; mi < 2; mi++)
                #pragma unroll
                for (int ni = 0; ni < 4; ni++) {
                    const int q = ni >> 1, p = (ni & 1) * 2;
                    mma_f16(acc[mi][ni], al[mi], bh[q][p], bh[q][p + 1]);
                }
        }

        // ---- epilogue: row side in regs; col side = in-thread fold + RED ----
        const float* sxb = reinterpret_cast<const float*>(sm + S_XNB + buf * 512);
        const int*   stb = reinterpret_cast<const int*>(sm + S_TGB + buf * 512);
        const bool offd = (bj > bi);

        #pragma unroll
        for (int ni = 0; ni < 4; ni++) {
            const int c0 = wn * 32 + ni * 8 + 2 * tq;      // local col 0..127
            const float xb0 = sxb[c0], xb1 = sxb[c0 + 1];
            const int tb0 = stb[c0], tb1 = stb[c0 + 1];
            const int j0 = jb + c0;
            // col-side per-column-stream fold state (value + source row)
            float bp0 = -FLT_MAX, bp1 = -FLT_MAX, bn0 = FLT_MAX, bn1 = FLT_MAX;
            int ip0 = 0, ip1 = 0, in0 = 0, in1 = 0;
            #pragma unroll
            for (int mi = 0; mi < 2; mi++) {
                #pragma unroll
                for (int h = 0; h < 2; h++) {
                    const int ri = mi * 2 + h;
                    const int gi = ib + wm * 32 + mi * 16 + h * 8 + rg;
                    const float d0 = acc[mi][ni][h * 2 + 0];
                    const float d1 = acc[mi][ni][h * 2 + 1];
                    const bool same0 = (tb0 == tga[ri]);
                    const bool same1 = (tb1 == tga[ri]);
                    // row side: candidate j for row i
                    float s0 = fmaf(-2.0f, d0, xb0);
                    float s1 = fmaf(-2.0f, d1, xb1);
                    if (same0) { if (s0 > rpv[ri]) { rpv[ri] = s0; rpi[ri] = j0; } }
                    else       { if (s0 < rnv[ri]) { rnv[ri] = s0; rni[ri] = j0; } }
                    if (same1) { if (s1 > rpv[ri]) { rpv[ri] = s1; rpi[ri] = j0 + 1; } }
                    else       { if (s1 < rnv[ri]) { rnv[ri] = s1; rni[ri] = j0 + 1; } }
                    // col side: candidate i for column j (ascending gi -> first-wins ties)
                    if (offd) {
                        float t0 = fmaf(-2.0f, d0, xna[ri]);
                        float t1 = fmaf(-2.0f, d1, xna[ri]);
                        if (same0) { if (t0 > bp0) { bp0 = t0; ip0 = gi; } }
                        else       { if (t0 < bn0) { bn0 = t0; in0 = gi; } }
                        if (same1) { if (t1 > bp1) { bp1 = t1; ip1 = gi; } }
                        else       { if (t1 < bn1) { bn1 = t1; in1 = gi; } }
                    }
                }
            }
            if (offd) {
                if (bp0 > -FLT_MAX)
                    red_max(&g_pkey[j0], ((u64)encf(bp0) << 32) | (uint32_t)(~(uint32_t)ip0));
                if (bn0 < FLT_MAX)
                    red_min(&g_nkey[j0], ((u64)encf(bn0) << 32) | (uint32_t)in0);
                if (bp1 > -FLT_MAX)
                    red_max(&g_pkey[j0 + 1], ((u64)encf(bp1) << 32) | (uint32_t)(~(uint32_t)ip1));
                if (bn1 < FLT_MAX)
                    red_min(&g_nkey[j0 + 1], ((u64)encf(bn1) << 32) | (uint32_t)in1);
            }
        }

        CPA_WAIT0();
        __syncthreads();
    }

    // ---- flush row-side running state ----
    #pragma unroll
    for (int r = 0; r < 4; r++) {
        float pv = rpv[r]; int pi2 = rpi[r];
        float nv = rnv[r]; int ni2 = rni[r];
        #pragma unroll
        for (int off = 1; off <= 2; off <<= 1) {
            float ov = __shfl_xor_sync(0xffffffffu, pv, off);
            int oi = __shfl_xor_sync(0xffffffffu, pi2, off);
            if (ov > pv || (ov == pv && oi < pi2)) { pv = ov; pi2 = oi; }
            ov = __shfl_xor_sync(0xffffffffu, nv, off);
            oi = __shfl_xor_sync(0xffffffffu, ni2, off);
            if (ov < nv || (ov == nv && oi < ni2)) { nv = ov; ni2 = oi; }
        }
        if (tq == 0) {
            int row = ib + wm * 32 + (r >> 1) * 16 + (r & 1) * 8 + rg;
            red_max(&g_pkey[row], ((u64)encf(pv) << 32) | (uint32_t)(~(uint32_t)pi2));
            red_min(&g_nkey[row], ((u64)encf(nv) << 32) | (uint32_t)ni2);
        }
    }
}

// ---------------- K3: decode keys, gather triplets (4 lanes per row) ----------------
__global__ void terms_kernel(const float* __restrict__ x, const int* __restrict__ tg) {
    __shared__ float red[4 * 9];
    int tid = threadIdx.x;                    // 0..127
    int lane = tid & 31, wrp = tid >> 5;
    int sub = tid & 3;
    int row = blockIdx.x * 32 + (tid >> 2);

    u64 pk = g_pkey[row], nk = g_nkey[row];
    int gp = (int)(~(uint32_t)pk);
    int gn = (int)((uint32_t)nk);

    int t = tg[row];
    int cs = g_hist[t];
    float vf = (cs > 1 && (NN - cs) >= 1) ? 1.0f : 0.0f;
    gp = min(max(gp, 0), NN - 1);
    gn = min(max(gn, 0), NN - 1);
    int ppos = g_ps[t * NN + gp] - 1;
    int pneg = gn - g_ps[t * NN + gn];
    ppos = min(max(ppos, 0), NN - 1);
    pneg = min(max(pneg, 0), NN - 1);

    const float4* A = reinterpret_cast<const float4*>(x) + (size_t)row * 32 + sub * 8;
    const float4* P = reinterpret_cast<const float4*>(x) + (size_t)ppos * 32 + sub * 8;
    const float4* Q = reinterpret_cast<const float4*>(x) + (size_t)pneg * 32 + sub * 8;
    float ap = 0, an = 0, npd = 0, l1a = 0, l1p = 0, l1n = 0;
    #pragma unroll
    for (int q = 0; q < 8; q++) {
        float4 a = A[q], p = P[q], n = Q[q];
        float d;
        d = a.x - p.x; ap = fmaf(d, d, ap);
        d = a.y - p.y; ap = fmaf(d, d, ap);
        d = a.z - p.z; ap = fmaf(d, d, ap);
        d = a.w - p.w; ap = fmaf(d, d, ap);
        d = a.x - n.x; an = fmaf(d, d, an);
        d = a.y - n.y; an = fmaf(d, d, an);
        d = a.z - n.z; an = fmaf(d, d, an);
        d = a.w - n.w; an = fmaf(d, d, an);
        d = p.x - n.x; npd = fmaf(d, d, npd);
        d = p.y - n.y; npd = fmaf(d, d, npd);
        d = p.z - n.z; npd = fmaf(d, d, npd);
        d = p.w - n.w; npd = fmaf(d, d, npd);
        l1a += fabsf(a.x) + fabsf(a.y) + fabsf(a.z) + fabsf(a.w);
        l1p += fabsf(p.x) + fabsf(p.y) + fabsf(p.z) + fabsf(p.w);
        l1n += fabsf(n.x) + fabsf(n.y) + fabsf(n.z) + fabsf(n.w);
    }
    // fold the 4 sub-lanes of this row (all lanes end with full sums)
    #pragma unroll
    for (int off = 1; off <= 2; off <<= 1) {
        ap  += __shfl_xor_sync(0xffffffffu, ap,  off);
        an  += __shfl_xor_sync(0xffffffffu, an,  off);
        npd += __shfl_xor_sync(0xffffffffu, npd, off);
        l1a += __shfl_xor_sync(0xffffffffu, l1a, off);
        l1p += __shfl_xor_sync(0xffffffffu, l1p, off);
        l1n += __shfl_xor_sync(0xffffffffu, l1n, off);
    }
    float tl = fmaxf(ap - an + FMARGIN, 0.0f) * vf;
    float m = (sub == 0) ? 1.0f : 0.0f;        // one lane per row contributes

    float vals[9];
    vals[0] = tl * m;
    vals[1] = ((tl > 0.0f) ? 1.0f : 0.0f) * m;
    vals[2] = l1a * vf * m;
    vals[3] = l1p * vf * m;
    vals[4] = l1n * vf * m;
    vals[5] = ap * vf * m;
    vals[6] = an * vf * m;
    vals[7] = (ap - an - npd) * vf * m;
    vals[8] = vf * m;

    #pragma unroll
    for (int k = 0; k < 9; k++) {
        float v = vals[k];
        #pragma unroll
        for (int o = 16; o > 0; o >>= 1) v += __shfl_down_sync(0xffffffffu, v, o);
        if (lane == 0) red[wrp * 9 + k] = v;
    }
    __syncthreads();
    if (tid < 9)
        g_part[blockIdx.x * 9 + tid] = red[tid] + red[9 + tid] + red[18 + tid] + red[27 + tid];
}

// ---------------- K4: finalize (parallel staging, ascending-block order) ----------------
__global__ void final_kernel(float* __restrict__ out, int out_size) {
    __shared__ float sp[256 * 9];
    __shared__ float s9[9];
    __shared__ float r[6];
    int tid = threadIdx.x;
    for (int i = tid; i < 256 * 9; i += blockDim.x) sp[i] = g_part[i];
    __syncthreads();
    if (tid < 9) {
        float s = 0.0f;
        for (int b = 0; b < 256; b++) s += sp[b * 9 + tid];
        s9[tid] = s;
    }
    __syncthreads();
    if (tid == 0) {
        float vcount = s9[8];
        float inv = (vcount > 0.0f) ? (1.0f / vcount) : 0.0f;
        float trip = (s9[1] > 0.0f) ? (s9[0] / s9[1]) : (s9[0] * inv);
        float sparse = (s9[2] + s9[3] + s9[4]) * inv * (1.0f / 3.0f);
        float pw = s9[7] * inv;
        if (pw < 0.0f) pw = 0.0f;
        r[0] = trip; r[1] = sparse; r[2] = pw;
        r[3] = vcount; r[4] = s9[5] * inv; r[5] = s9[6] * inv;
    }
    __syncthreads();
    for (int i = tid; i < out_size; i += blockDim.x)
        out[i] = (i < 6) ? r[i] : 0.0f;
}

// ---------------- launch ----------------
extern "C" void kernel_launch(void* const* d_in, const int* in_sizes, int n_in,
                              void* d_out, int out_size) {
    const float* x = (const float*)d_in[0];
    const int* tg = (const int*)d_in[1];

    cudaFuncSetAttribute(dist_mma_kernel, cudaFuncAttributeMaxDynamicSharedMemorySize,
                         S_TOT);

    prep_kernel<<<64, 256>>>(x);
    prefix_kernel<<<CC, 1024>>>(tg);
    dist_mma_kernel<<<NCTAS, NTHREADS, S_TOT>>>(tg);
    terms_kernel<<<256, 128>>>(x, tg);
    final_kernel<<<1, 1024>>>((float*)d_out, out_size);
}